// round 12
// baseline (speedup 1.0000x reference)
#include <cuda_runtime.h>

#define HW   256
#define PS   113      // (256-32)/2 + 1
#define PP   130      // padded row stride for P (even -> aligned float2 STS)
#define PRS  129      // padded row stride for pr table
#define BSTR 130      // base table stride
#define BASE_OFF (128 * PP + 113 * PRS)
#define RED_OFF  (BASE_OFF + 16 * BSTR)
#define NT   1024

// smem (floats):
//   P    : 128*130  (slice-relative prefixes, slices of 8 pair-rows)
//   pr   : 113*129  (pair-column window sums)
//   base : 16*130   (prefix of slice totals per pair-column)
//   redMaxHi/Lo, redMinHi/Lo : 32 u32 each; rects : 8 int
#define SMEM_FLOATS (RED_OFF + 32 * 4 + 8)
#define SMEM_BYTES  (SMEM_FLOATS * 4)

__device__ __forceinline__ void st_stream_f32(float* p, float v) {
    asm volatile("st.global.cs.f32 [%0], %1;" :: "l"(p), "f"(v) : "memory");
}
__device__ __forceinline__ void st_stream_f2(float2* p, float2 v) {
    asm volatile("st.global.cs.v2.f32 [%0], {%1, %2};"
                 :: "l"(p), "f"(v.x), "f"(v.y) : "memory");
}
__device__ __forceinline__ void st_stream_f4(float4* p, float4 v) {
    asm volatile("st.global.cs.v4.f32 [%0], {%1, %2, %3, %4};"
                 :: "l"(p), "f"(v.x), "f"(v.y), "f"(v.z), "f"(v.w) : "memory");
}
__device__ __forceinline__ float sigm(float d) { return __fdividef(1.0f, 1.0f + __expf(-d)); }

extern "C" __global__ void __launch_bounds__(NT, 1)
genmask_kernel(const float* __restrict__ infeat, float* __restrict__ out, int mask_off)
{
    extern __shared__ float smem[];
    float* P    = smem;                                 // [128][PP]
    float* pr   = smem + 128 * PP;                      // [113][PRS]
    float* base = smem + BASE_OFF;                      // [16][BSTR]
    unsigned* redMaxHi = (unsigned*)(smem + RED_OFF);   // [32]
    unsigned* redMaxLo = redMaxHi + 32;
    unsigned* redMinHi = redMaxLo + 32;
    unsigned* redMinLo = redMinHi + 32;
    int*      rects    = (int*)(redMinLo + 32);         // [8]

    const int b   = blockIdx.x;
    const int tid = threadIdx.x;

    const float* base0 = infeat + (size_t)b * 2 * HW * HW;   // channel 0
    const float* base1 = base0 + HW * HW;                    // channel 1
    float* mout = out + (size_t)mask_off + (size_t)b * HW * HW;

    // ---- Phase 1: float4 loads; 2x2-summed sigmoid prefixes per pair-column ----
    // thread t: quad-col qc = t&63 (cols 4qc..4qc+3), slice s = t>>6 owns
    // pair-rows [8s..8s+7]. Zero-fill of the mask is interleaved (streaming).
    {
        const int qc = tid & 63;
        const int s  = tid >> 6;
        const float4* c0 = (const float4*)(base0 + (size_t)(16 * s) * HW) + qc;
        const float4* c1 = (const float4*)(base1 + (size_t)(16 * s) * HW) + qc;
        float2* Pw = (float2*)(P + (8 * s) * PP) + qc;   // two pair-cols per thread
        float4* zb = (float4*)mout + tid;
        const float4 zero4 = make_float4(0.f, 0.f, 0.f, 0.f);
        float r0 = 0.0f, r1 = 0.0f;
        #pragma unroll
        for (int j = 0; j < 8; j++) {
            const float4 a0 = c0[(size_t)(2 * j) * (HW / 4)];
            const float4 a1 = c1[(size_t)(2 * j) * (HW / 4)];
            const float4 b0 = c0[(size_t)(2 * j + 1) * (HW / 4)];
            const float4 b1 = c1[(size_t)(2 * j + 1) * (HW / 4)];
            st_stream_f4(zb + (2 * j) * NT, zero4);
            st_stream_f4(zb + (2 * j + 1) * NT, zero4);
            r0 += sigm(a0.x - a1.x) + sigm(a0.y - a1.y)
                + sigm(b0.x - b1.x) + sigm(b0.y - b1.y);
            r1 += sigm(a0.z - a1.z) + sigm(a0.w - a1.w)
                + sigm(b0.z - b1.z) + sigm(b0.w - b1.w);
            Pw[j * (PP / 2)] = make_float2(r0, r1);      // slice-relative prefix
        }
    }
    __syncthreads();

    // ---- base[s][pc] = sum of slice totals for slices < s (per pair-column) ----
    if (tid < 128) {
        const int pc = tid;
        float acc = 0.0f;
        #pragma unroll
        for (int s = 0; s < 16; s++) {
            base[s * BSTR + pc] = acc;
            acc += P[(8 * s + 7) * PP + pc];             // slice total (relative last)
        }
    }
    __syncthreads();

    // ---- Phase 2a: pr[yo][pc] = absolute window sum over pair-rows [yo, yo+15] ----
    for (int i = tid; i < PS * 128; i += NT) {
        const int yo = i >> 7;
        const int pc = i & 127;
        const int hi = yo + 15;
        float v = P[hi * PP + pc] + base[(hi >> 3) * BSTR + pc];
        if (yo > 0) {
            const int lo = yo - 1;
            v -= P[lo * PP + pc] + base[(lo >> 3) * BSTR + pc];
        }
        pr[yo * PRS + pc] = v;
    }
    __syncthreads();

    // ---- Phase 2b: (row, eighth-segment) incremental horizontal slide ----
    float bestMax = -1.0f;
    float bestMin = 1e30f;
    int   idxMax  = 0, idxMin = 0;

    if (tid < 904) {                           // 113 rows x 8 segments
        const int row = tid >> 3;
        const int seg = tid & 7;
        const int px0 = (seg == 0) ? 0 : 15 + 14 * (seg - 1);   // 0,15,29,...,99
        const int cnt = (seg == 0) ? 15 : 14;                   // 15 + 14*7 = 113
        const float* prr = pr + row * PRS;

        float H = 0.0f;
        #pragma unroll
        for (int i = 0; i < 16; i++) H += prr[px0 + i];

        for (int s = 0; s < cnt; s++) {
            const int px   = px0 + s;
            const int fidx = row * PS + px;
            if (H > bestMax) { bestMax = H; idxMax = fidx; }  // strict -> first index
            if (H < bestMin) { bestMin = H; idxMin = fidx; }
            if (s + 1 < cnt) H += prr[px + 16] - prr[px];
        }
    }

    // ---- Arg reduction ----
    unsigned long long kMax, kMin;
    if (tid < 904) {
        kMax = ((unsigned long long)__float_as_uint(bestMax) << 32)
             | (unsigned long long)(0xFFFFFFFFu - (unsigned)idxMax);
        kMin = ((unsigned long long)__float_as_uint(bestMin) << 32)
             | (unsigned long long)(unsigned)idxMin;
    } else {
        kMax = 0ull;
        kMin = ~0ull;
    }
    #pragma unroll
    for (int o = 16; o > 0; o >>= 1) {
        unsigned long long v;
        v = __shfl_xor_sync(0xFFFFFFFFu, kMax, o); if (v > kMax) kMax = v;
        v = __shfl_xor_sync(0xFFFFFFFFu, kMin, o); if (v < kMin) kMin = v;
    }
    const int warp = tid >> 5;
    if ((tid & 31) == 0) {
        redMaxHi[warp] = (unsigned)(kMax >> 32);
        redMaxLo[warp] = (unsigned)(kMax & 0xFFFFFFFFull);
        redMinHi[warp] = (unsigned)(kMin >> 32);
        redMinLo[warp] = (unsigned)(kMin & 0xFFFFFFFFull);
    }
    __syncthreads();

    if (tid == 0) {
        kMax = ((unsigned long long)redMaxHi[0] << 32) | redMaxLo[0];
        kMin = ((unsigned long long)redMinHi[0] << 32) | redMinLo[0];
        #pragma unroll
        for (int w = 1; w < 32; w++) {
            unsigned long long vmx = ((unsigned long long)redMaxHi[w] << 32) | redMaxLo[w];
            unsigned long long vmn = ((unsigned long long)redMinHi[w] << 32) | redMinLo[w];
            if (vmx > kMax) kMax = vmx;
            if (vmn < kMin) kMin = vmn;
        }
        const int i0 = (int)(0xFFFFFFFFu - (unsigned)(kMax & 0xFFFFFFFFull)); // class 0
        const int i1 = (int)(kMin & 0xFFFFFFFFull);                           // class 1
        const int px0 = i0 % PS, py0 = i0 / PS;
        const int px1 = i1 % PS, py1 = i1 / PS;
        int r[8] = { 2 * px0, 2 * px0 + 31, 2 * py0, 2 * py0 + 31,
                     2 * px1, 2 * px1 + 31, 2 * py1, 2 * py1 + 31 };
        float* oxy = out + (size_t)b * 8;
        #pragma unroll
        for (int i = 0; i < 8; i++) { st_stream_f32(oxy + i, (float)r[i]); rects[i] = r[i]; }
    }
    __syncthreads();

    // ---- Phase 3: write ONLY the two 32x32 rects of ones (zeros already streamed) ----
    // 1024 threads: rect = tid>>9, row-in-rect = (tid>>4)&31, seg = tid&15 -> 2 cols.
    {
        const int rrect = tid >> 9;
        const int ri    = (tid >> 4) & 31;
        const int seg   = tid & 15;
        const int ox0 = rects[4 * rrect + 0];
        const int oy0 = rects[4 * rrect + 2];
        const int row = oy0 + ri;
        float2* dst = (float2*)(mout + (size_t)row * HW + ox0) + seg;  // ox0 even
        st_stream_f2(dst, make_float2(1.0f, 1.0f));
    }
}

extern "C" void kernel_launch(void* const* d_in, const int* in_sizes, int n_in,
                              void* d_out, int out_size)
{
    const float* infeat = (const float*)d_in[0];
    const int B = in_sizes[0] / (2 * HW * HW);          // 128
    const int mask_off = out_size - B * HW * HW;        // oxy occupies the front (B*8)

    cudaFuncSetAttribute(genmask_kernel,
                         cudaFuncAttributeMaxDynamicSharedMemorySize, SMEM_BYTES);
    genmask_kernel<<<B, NT, SMEM_BYTES>>>(infeat, (float*)d_out, mask_off);
}

// round 16
// speedup vs baseline: 1.1092x; 1.1092x over previous
#include <cuda_runtime.h>

#define HW   256
#define PS   113      // (256-32)/2 + 1
#define PP   130      // padded row stride for P (even -> aligned float2 STS)
#define PRS  129      // padded row stride for pr table
#define BSTR 130      // base table stride
#define BASE_OFF (128 * PP + 113 * PRS)
#define RED_OFF  (BASE_OFF + 16 * BSTR)
#define NT   1024

// smem (floats):
//   P    : 128*130  (slice-relative prefixes, slices of 8 pair-rows)
//   pr   : 113*129  (pair-column window sums)
//   base : 16*130   (prefix of slice totals per pair-column)
//   redMaxHi/Lo, redMinHi/Lo : 32 u32 each; rects : 8 int
#define SMEM_FLOATS (RED_OFF + 32 * 4 + 8)
#define SMEM_BYTES  (SMEM_FLOATS * 4)

__device__ __forceinline__ void st_stream_f32(float* p, float v) {
    asm volatile("st.global.cs.f32 [%0], %1;" :: "l"(p), "f"(v) : "memory");
}
__device__ __forceinline__ void st_stream_f2(float2* p, float2 v) {
    asm volatile("st.global.cs.v2.f32 [%0], {%1, %2};"
                 :: "l"(p), "f"(v.x), "f"(v.y) : "memory");
}
__device__ __forceinline__ void st_stream_f4(float4* p, float4 v) {
    asm volatile("st.global.cs.v4.f32 [%0], {%1, %2, %3, %4};"
                 :: "l"(p), "f"(v.x), "f"(v.y), "f"(v.z), "f"(v.w) : "memory");
}
// L2 evict-last access policy (sm_80+ cache_hint path; legal for v4.f32).
__device__ __forceinline__ unsigned long long mk_evl_policy() {
    unsigned long long pol;
    asm volatile("createpolicy.fractional.L2::evict_last.b64 %0, 1.0;" : "=l"(pol));
    return pol;
}
__device__ __forceinline__ float4 ld_evl_f4(const float4* p, unsigned long long pol) {
    float4 v;
    asm volatile("ld.global.L2::cache_hint.v4.f32 {%0, %1, %2, %3}, [%4], %5;"
                 : "=f"(v.x), "=f"(v.y), "=f"(v.z), "=f"(v.w) : "l"(p), "l"(pol));
    return v;
}
__device__ __forceinline__ float sigm(float d) { return __fdividef(1.0f, 1.0f + __expf(-d)); }

extern "C" __global__ void __launch_bounds__(NT, 1)
genmask_kernel(const float* __restrict__ infeat, float* __restrict__ out, int mask_off)
{
    extern __shared__ float smem[];
    float* P    = smem;                                 // [128][PP]
    float* pr   = smem + 128 * PP;                      // [113][PRS]
    float* base = smem + BASE_OFF;                      // [16][BSTR]
    unsigned* redMaxHi = (unsigned*)(smem + RED_OFF);   // [32]
    unsigned* redMaxLo = redMaxHi + 32;
    unsigned* redMinHi = redMaxLo + 32;
    unsigned* redMinLo = redMinHi + 32;
    int*      rects    = (int*)(redMinLo + 32);         // [8]

    const int b   = blockIdx.x;
    const int tid = threadIdx.x;

    const float* base0 = infeat + (size_t)b * 2 * HW * HW;   // channel 0
    const float* base1 = base0 + HW * HW;                    // channel 1
    float* mout = out + (size_t)mask_off + (size_t)b * HW * HW;

    // ---- Phase 1: L2-persistent float4 loads; 2x2-summed sigmoid prefixes ----
    // thread t: quad-col qc = t&63 (cols 4qc..4qc+3), slice s = t>>6 owns
    // pair-rows [8s..8s+7]. Zero-fill of the mask is interleaved (streaming).
    {
        const unsigned long long pol = mk_evl_policy();
        const int qc = tid & 63;
        const int s  = tid >> 6;
        const float4* c0 = (const float4*)(base0 + (size_t)(16 * s) * HW) + qc;
        const float4* c1 = (const float4*)(base1 + (size_t)(16 * s) * HW) + qc;
        float2* Pw = (float2*)(P + (8 * s) * PP) + qc;   // two pair-cols per thread
        float4* zb = (float4*)mout + tid;
        const float4 zero4 = make_float4(0.f, 0.f, 0.f, 0.f);
        float r0 = 0.0f, r1 = 0.0f;
        #pragma unroll
        for (int j = 0; j < 8; j++) {
            const float4 a0 = ld_evl_f4(c0 + (size_t)(2 * j) * (HW / 4), pol);
            const float4 a1 = ld_evl_f4(c1 + (size_t)(2 * j) * (HW / 4), pol);
            const float4 b0 = ld_evl_f4(c0 + (size_t)(2 * j + 1) * (HW / 4), pol);
            const float4 b1 = ld_evl_f4(c1 + (size_t)(2 * j + 1) * (HW / 4), pol);
            st_stream_f4(zb + (2 * j) * NT, zero4);
            st_stream_f4(zb + (2 * j + 1) * NT, zero4);
            r0 += sigm(a0.x - a1.x) + sigm(a0.y - a1.y)
                + sigm(b0.x - b1.x) + sigm(b0.y - b1.y);
            r1 += sigm(a0.z - a1.z) + sigm(a0.w - a1.w)
                + sigm(b0.z - b1.z) + sigm(b0.w - b1.w);
            Pw[j * (PP / 2)] = make_float2(r0, r1);      // slice-relative prefix
        }
    }
    __syncthreads();

    // ---- base[s][pc] = sum of slice totals for slices < s (per pair-column) ----
    if (tid < 128) {
        const int pc = tid;
        float acc = 0.0f;
        #pragma unroll
        for (int s = 0; s < 16; s++) {
            base[s * BSTR + pc] = acc;
            acc += P[(8 * s + 7) * PP + pc];             // slice total (relative last)
        }
    }
    __syncthreads();

    // ---- Phase 2a: pr[yo][pc] = absolute window sum over pair-rows [yo, yo+15] ----
    for (int i = tid; i < PS * 128; i += NT) {
        const int yo = i >> 7;
        const int pc = i & 127;
        const int hi = yo + 15;
        float v = P[hi * PP + pc] + base[(hi >> 3) * BSTR + pc];
        if (yo > 0) {
            const int lo = yo - 1;
            v -= P[lo * PP + pc] + base[(lo >> 3) * BSTR + pc];
        }
        pr[yo * PRS + pc] = v;
    }
    __syncthreads();

    // ---- Phase 2b: (row, eighth-segment) incremental horizontal slide ----
    float bestMax = -1.0f;
    float bestMin = 1e30f;
    int   idxMax  = 0, idxMin = 0;

    if (tid < 904) {                           // 113 rows x 8 segments
        const int row = tid >> 3;
        const int seg = tid & 7;
        const int px0 = (seg == 0) ? 0 : 15 + 14 * (seg - 1);   // 0,15,29,...,99
        const int cnt = (seg == 0) ? 15 : 14;                   // 15 + 14*7 = 113
        const float* prr = pr + row * PRS;

        float H = 0.0f;
        #pragma unroll
        for (int i = 0; i < 16; i++) H += prr[px0 + i];

        for (int s = 0; s < cnt; s++) {
            const int px   = px0 + s;
            const int fidx = row * PS + px;
            if (H > bestMax) { bestMax = H; idxMax = fidx; }  // strict -> first index
            if (H < bestMin) { bestMin = H; idxMin = fidx; }
            if (s + 1 < cnt) H += prr[px + 16] - prr[px];
        }
    }

    // ---- Arg reduction ----
    unsigned long long kMax, kMin;
    if (tid < 904) {
        kMax = ((unsigned long long)__float_as_uint(bestMax) << 32)
             | (unsigned long long)(0xFFFFFFFFu - (unsigned)idxMax);
        kMin = ((unsigned long long)__float_as_uint(bestMin) << 32)
             | (unsigned long long)(unsigned)idxMin;
    } else {
        kMax = 0ull;
        kMin = ~0ull;
    }
    #pragma unroll
    for (int o = 16; o > 0; o >>= 1) {
        unsigned long long v;
        v = __shfl_xor_sync(0xFFFFFFFFu, kMax, o); if (v > kMax) kMax = v;
        v = __shfl_xor_sync(0xFFFFFFFFu, kMin, o); if (v < kMin) kMin = v;
    }
    const int warp = tid >> 5;
    if ((tid & 31) == 0) {
        redMaxHi[warp] = (unsigned)(kMax >> 32);
        redMaxLo[warp] = (unsigned)(kMax & 0xFFFFFFFFull);
        redMinHi[warp] = (unsigned)(kMin >> 32);
        redMinLo[warp] = (unsigned)(kMin & 0xFFFFFFFFull);
    }
    __syncthreads();

    if (tid == 0) {
        kMax = ((unsigned long long)redMaxHi[0] << 32) | redMaxLo[0];
        kMin = ((unsigned long long)redMinHi[0] << 32) | redMinLo[0];
        #pragma unroll
        for (int w = 1; w < 32; w++) {
            unsigned long long vmx = ((unsigned long long)redMaxHi[w] << 32) | redMaxLo[w];
            unsigned long long vmn = ((unsigned long long)redMinHi[w] << 32) | redMinLo[w];
            if (vmx > kMax) kMax = vmx;
            if (vmn < kMin) kMin = vmn;
        }
        const int i0 = (int)(0xFFFFFFFFu - (unsigned)(kMax & 0xFFFFFFFFull)); // class 0
        const int i1 = (int)(kMin & 0xFFFFFFFFull);                           // class 1
        const int px0 = i0 % PS, py0 = i0 / PS;
        const int px1 = i1 % PS, py1 = i1 / PS;
        int r[8] = { 2 * px0, 2 * px0 + 31, 2 * py0, 2 * py0 + 31,
                     2 * px1, 2 * px1 + 31, 2 * py1, 2 * py1 + 31 };
        float* oxy = out + (size_t)b * 8;
        #pragma unroll
        for (int i = 0; i < 8; i++) { st_stream_f32(oxy + i, (float)r[i]); rects[i] = r[i]; }
    }
    __syncthreads();

    // ---- Phase 3: write ONLY the two 32x32 rects of ones (zeros already streamed) ----
    // 1024 threads: rect = tid>>9, row-in-rect = (tid>>4)&31, seg = tid&15 -> 2 cols.
    {
        const int rrect = tid >> 9;
        const int ri    = (tid >> 4) & 31;
        const int seg   = tid & 15;
        const int ox0 = rects[4 * rrect + 0];
        const int oy0 = rects[4 * rrect + 2];
        const int row = oy0 + ri;
        float2* dst = (float2*)(mout + (size_t)row * HW + ox0) + seg;  // ox0 even
        st_stream_f2(dst, make_float2(1.0f, 1.0f));
    }
}

extern "C" void kernel_launch(void* const* d_in, const int* in_sizes, int n_in,
                              void* d_out, int out_size)
{
    const float* infeat = (const float*)d_in[0];
    const int B = in_sizes[0] / (2 * HW * HW);          // 128
    const int mask_off = out_size - B * HW * HW;        // oxy occupies the front (B*8)

    cudaFuncSetAttribute(genmask_kernel,
                         cudaFuncAttributeMaxDynamicSharedMemorySize, SMEM_BYTES);
    genmask_kernel<<<B, NT, SMEM_BYTES>>>(infeat, (float*)d_out, mask_off);
}